// round 10
// baseline (speedup 1.0000x reference)
#include <cuda_runtime.h>

#define B 64
#define CIN 512
#define HIDE 128
#define OP 512
#define HW 4096   // 64*64
#define SENT 0x7FC00123u   // quiet-NaN sentinel; finite means can never equal it

__device__ float g_y[B * CIN];   // pooled values (sentinel-filled by init)

__device__ __forceinline__ float ld_cg(const float* p) {
    float v;
    asm volatile("ld.global.cg.f32 %0, [%1];" : "=f"(v) : "l"(p));
    return v;
}

// fill g_y with sentinel (32 blocks x 256 threads x 1 float4)
__global__ __launch_bounds__(256) void init_kernel() {
    const int i = blockIdx.x * 256 + threadIdx.x;  // 0..8191
    const float s = __uint_as_float(SENT);
    reinterpret_cast<float4*>(g_y)[i] = make_float4(s, s, s, s);
}

// ---------------------------------------------------------------------------
// Fused kernel. bids 0..63: head blocks (poll sentinel, then compute batch).
// bids 64..32831: pool blocks — EXACT proven R4 body, no fences, no atomics.
// ---------------------------------------------------------------------------
__global__ void __launch_bounds__(256, 8) fused_kernel(const float* __restrict__ x,
                                                       const float* __restrict__ W1,
                                                       const float* __restrict__ A2,
                                                       const float* __restrict__ w2p,
                                                       const float* __restrict__ w3p,
                                                       const float* __restrict__ W4,
                                                       float* __restrict__ out) {
    const int tid  = threadIdx.x;
    const int wid  = tid >> 5;
    const int lane = tid & 31;

    __shared__ float ys[CIN];
    __shared__ float y1s[HIDE];
    __shared__ float a1s[HIDE];
    __shared__ float y3s[HIDE];
    __shared__ float red[8];

    if (blockIdx.x >= B) {
        // ================= POOL BLOCK (unperturbed R4 body) =================
        const int row = blockIdx.x - B;
        const float4* p = reinterpret_cast<const float4*>(x + (size_t)row * HW);

        float s = 0.0f;
#pragma unroll
        for (int i = 0; i < 4; i++) {
            float4 v = __ldcs(&p[tid + i * 256]);
            s += (v.x + v.y) + (v.z + v.w);
        }
#pragma unroll
        for (int o = 16; o > 0; o >>= 1) s += __shfl_xor_sync(0xFFFFFFFFu, s, o);

        if (lane == 0) red[wid] = s;
        __syncthreads();
        if (tid < 8) {
            float v = red[tid];
#pragma unroll
            for (int o = 4; o > 0; o >>= 1) v += __shfl_xor_sync(0x000000FFu, v, o);
            if (tid == 0) g_y[row] = v * (1.0f / (float)HW);
        }
        return;
    }

    // ================= HEAD BLOCK (batch b) =================
    const int b = blockIdx.x;
    const float* gyb = g_y + b * CIN;

    // fence-free data-gated wait: a non-sentinel value IS the final datum
    {
        float a0 = ld_cg(gyb + tid);
        while (__float_as_uint(a0) == SENT) { __nanosleep(256); a0 = ld_cg(gyb + tid); }
        float a1 = ld_cg(gyb + tid + 256);
        while (__float_as_uint(a1) == SENT) { __nanosleep(256); a1 = ld_cg(gyb + tid + 256); }
        ys[tid]       = a0;
        ys[tid + 256] = a1;
    }
    __syncthreads();

    // ---- GEMV1: warp wid owns h in [wid*16, wid*16+16): 2 passes of 8 ----
#pragma unroll
    for (int pass = 0; pass < 2; pass++) {
        const int h0 = (wid << 4) + (pass << 3);
        float acc[8];
#pragma unroll
        for (int i = 0; i < 8; i++) acc[i] = 0.0f;
#pragma unroll
        for (int k = 0; k < CIN / 32; k++) {
            const int c = lane + (k << 5);
            const float yv = ys[c];
#pragma unroll
            for (int i = 0; i < 8; i++)
                acc[i] += yv * __ldg(&W1[(size_t)(h0 + i) * CIN + c]);
        }
#pragma unroll
        for (int o = 16; o > 0; o >>= 1)
#pragma unroll
            for (int i = 0; i < 8; i++)
                acc[i] += __shfl_xor_sync(0xFFFFFFFFu, acc[i], o);
        if (lane == 0)
#pragma unroll
            for (int i = 0; i < 8; i++) y1s[h0 + i] = acc[i];
    }
    __syncthreads();

    // ---- softmax(w2 * y1) over 128 channels (warps 0..3) ----
    const float w2 = __ldg(w2p);
    if (tid < HIDE) {
        const float z = w2 * y1s[tid];
        float m = z;
#pragma unroll
        for (int o = 16; o > 0; o >>= 1) m = fmaxf(m, __shfl_xor_sync(0xFFFFFFFFu, m, o));
        if (lane == 0) red[wid] = m;
    }
    __syncthreads();
    if (tid < HIDE) {
        const float m = fmaxf(fmaxf(red[0], red[1]), fmaxf(red[2], red[3]));
        const float e = expf(w2 * y1s[tid] - m);
        a1s[tid] = e;
        float ssum = e;
#pragma unroll
        for (int o = 16; o > 0; o >>= 1) ssum += __shfl_xor_sync(0xFFFFFFFFu, ssum, o);
        if (lane == 0) red[4 + wid] = ssum;
    }
    __syncthreads();

    // ---- y2/y3: h = tid (<128); A2 coalesced over h ----
    if (tid < HIDE) {
        const float ssum = (red[4] + red[5]) + (red[6] + red[7]);
        const float a1n = a1s[tid] / ssum;
        float t = y1s[tid] * a1n;
#pragma unroll 16
        for (int j = 0; j < HIDE; j++) t += y1s[j] * __ldg(&A2[j * HIDE + tid]);
        const float w3 = __ldg(w3p);
        y3s[tid] = fmaxf(w3 * t, 0.0f);
    }
    __syncthreads();

    // ---- GEMV4: warp wid owns o in [wid*64, wid*64+64): 8 passes of 8 ----
#pragma unroll
    for (int pass = 0; pass < 8; pass++) {
        const int o0 = (wid << 6) + (pass << 3);
        float acc[8];
#pragma unroll
        for (int i = 0; i < 8; i++) acc[i] = 0.0f;
#pragma unroll
        for (int k = 0; k < HIDE / 32; k++) {
            const int j = lane + (k << 5);
            const float yv = y3s[j];
#pragma unroll
            for (int i = 0; i < 8; i++)
                acc[i] += yv * __ldg(&W4[(size_t)(o0 + i) * HIDE + j]);
        }
#pragma unroll
        for (int off = 16; off > 0; off >>= 1)
#pragma unroll
            for (int i = 0; i < 8; i++)
                acc[i] += __shfl_xor_sync(0xFFFFFFFFu, acc[i], off);
        if (lane == 0) {
#pragma unroll
            for (int i = 0; i < 8; i++)
                out[b * OP + o0 + i] = 1.0f / (1.0f + expf(-acc[i]));
        }
    }
}

extern "C" void kernel_launch(void* const* d_in, const int* in_sizes, int n_in,
                              void* d_out, int out_size) {
    const float* x  = (const float*)d_in[0];
    const float* W1 = (const float*)d_in[1];
    const float* A2 = (const float*)d_in[2];
    const float* w2 = (const float*)d_in[3];
    const float* w3 = (const float*)d_in[4];
    const float* W4 = (const float*)d_in[5];
    float* out = (float*)d_out;

    init_kernel<<<32, 256>>>();
    fused_kernel<<<B * CIN + B, 256>>>(x, W1, A2, w2, w3, W4, out);
}